// round 1
// baseline (speedup 1.0000x reference)
#include <cuda_runtime.h>
#include <cuda_bf16.h>
#include <cstdint>

// Problem constants
#define BSZ 8
#define SEQ 1024
#define DMODEL 512
#define NH 8
#define DK 64
#define STATIONS 128
#define ROWS (BSZ * SEQ)          // 8192
#define QKVLD 1536                // q|k|v concatenated per row

// Scratch (static device globals; no runtime allocation)
__device__ float g_qkv[ROWS * QKVLD];     // [8192][1536] = q|k|v
__device__ float g_ctx[ROWS * DMODEL];    // attention output, [b,i,h*64+d]
__device__ float g_y[ROWS * DMODEL];      // fc output pre-LN

// ---------------------------------------------------------------------------
// SGEMM body: C[m0:m0+128, c0:c0+128] = A[m0:,:512] @ B[n0:n0+128,:512]^T
// BM=BN=128, BK=8, 256 threads, 8x8 microtile.
// ---------------------------------------------------------------------------
__device__ __forceinline__ void sgemm_body(const float* __restrict__ A,
                                           const float* __restrict__ B,
                                           float* __restrict__ C,
                                           int m0, int n0, int c0, int ldc)
{
    __shared__ float As[8][128];
    __shared__ float Bs[8][128];
    const int tid  = threadIdx.x;
    const int lrow = tid >> 1;           // 0..127
    const int lcol = (tid & 1) << 2;     // 0 or 4
    const float* Ap = A + (size_t)(m0 + lrow) * 512 + lcol;
    const float* Bp = B + (size_t)(n0 + lrow) * 512 + lcol;

    float acc[8][8];
#pragma unroll
    for (int i = 0; i < 8; i++)
#pragma unroll
        for (int j = 0; j < 8; j++) acc[i][j] = 0.f;

    const int tx = tid & 15;   // -> n
    const int ty = tid >> 4;   // -> m

#pragma unroll 2
    for (int kt = 0; kt < 512; kt += 8) {
        float4 av = *(const float4*)(Ap + kt);
        float4 bv = *(const float4*)(Bp + kt);
        As[lcol + 0][lrow] = av.x; As[lcol + 1][lrow] = av.y;
        As[lcol + 2][lrow] = av.z; As[lcol + 3][lrow] = av.w;
        Bs[lcol + 0][lrow] = bv.x; Bs[lcol + 1][lrow] = bv.y;
        Bs[lcol + 2][lrow] = bv.z; Bs[lcol + 3][lrow] = bv.w;
        __syncthreads();
#pragma unroll
        for (int k = 0; k < 8; k++) {
            float a[8], b[8];
            *(float4*)(a)     = *(const float4*)(&As[k][ty * 4]);
            *(float4*)(a + 4) = *(const float4*)(&As[k][64 + ty * 4]);
            *(float4*)(b)     = *(const float4*)(&Bs[k][tx * 4]);
            *(float4*)(b + 4) = *(const float4*)(&Bs[k][64 + tx * 4]);
#pragma unroll
            for (int i = 0; i < 8; i++)
#pragma unroll
                for (int j = 0; j < 8; j++)
                    acc[i][j] += a[i] * b[j];
        }
        __syncthreads();
    }

#pragma unroll
    for (int ih = 0; ih < 2; ih++) {
#pragma unroll
        for (int i = 0; i < 4; i++) {
            int m = m0 + ih * 64 + ty * 4 + i;
            float* Crow = C + (size_t)m * ldc + c0;
            *(float4*)(Crow + tx * 4)      = *(float4*)(&acc[ih * 4 + i][0]);
            *(float4*)(Crow + 64 + tx * 4) = *(float4*)(&acc[ih * 4 + i][4]);
        }
    }
}

// QKV: C = hs @ [Wq|Wk|Wv]^T  -> g_qkv [8192][1536]
__global__ __launch_bounds__(256) void sgemm_qkv(const float* __restrict__ hs,
                                                 const float* __restrict__ Wq,
                                                 const float* __restrict__ Wk,
                                                 const float* __restrict__ Wv)
{
    int m0 = blockIdx.x * 128;
    int gcol = blockIdx.y * 128;
    const float* B = (gcol < 512) ? Wq : (gcol < 1024 ? Wk : Wv);
    int n0 = gcol & 511;
    sgemm_body(hs, B, g_qkv, m0, n0, gcol, QKVLD);
}

// FC: g_y = g_ctx @ fc_w^T
__global__ __launch_bounds__(256) void sgemm_fc(const float* __restrict__ fcw)
{
    int m0 = blockIdx.x * 128;
    int n0 = blockIdx.y * 128;
    sgemm_body(g_ctx, fcw, g_y, m0, n0, n0, DMODEL);
}

// ---------------------------------------------------------------------------
// Sparse star attention. Block = (qtile 0..15, h, b), 256 threads (8 warps),
// each warp handles 8 queries. K stations transposed in smem (stride 129),
// then same smem reused for V (stride 65).
// ---------------------------------------------------------------------------
__global__ __launch_bounds__(256) void attn_kernel(const float* __restrict__ rpe)
{
    __shared__ float sm[128 * 65];   // max(64*129=8256, 128*65=8320) floats

    const int b = blockIdx.z, h = blockIdx.y, qt = blockIdx.x;
    const int tid = threadIdx.x, lane = tid & 31, w = tid >> 5;

    const float* qbase = g_qkv + (size_t)b * SEQ * QKVLD + h * 64;
    const float* kbase = qbase + 512;
    const float* vbase = qbase + 1024;

    // Phase 1: K stations transposed: sm[d*129 + j] = k[b,j,h,d]
    for (int idx = tid; idx < STATIONS * 64; idx += 256) {
        int j = idx >> 6, d = idx & 63;
        sm[d * 129 + j] = kbase[(size_t)j * QKVLD + d];
    }
    __syncthreads();

    float P[8][4];
    float PD[8];
    const int i0 = qt * 64 + w * 8;

#pragma unroll
    for (int qq = 0; qq < 8; qq++) {
        const int i = i0 + qq;
        const float* qrow = qbase + (size_t)i * QKVLD;
        const float qa = qrow[lane], qb = qrow[lane + 32];

        float s[4] = {0.f, 0.f, 0.f, 0.f};
#pragma unroll
        for (int d = 0; d < 64; d++) {
            float qd = __shfl_sync(0xffffffffu, (d < 32 ? qa : qb), d & 31);
            const float* Kd = &sm[d * 129];
            s[0] += qd * Kd[lane];
            s[1] += qd * Kd[lane + 32];
            s[2] += qd * Kd[lane + 64];
            s[3] += qd * Kd[lane + 96];
        }
        const float* rrow = rpe + (((size_t)(b * NH + h) * SEQ + i) * SEQ);
        s[0] += rrow[lane];      s[1] += rrow[lane + 32];
        s[2] += rrow[lane + 64]; s[3] += rrow[lane + 96];

        // diagonal (self) term, only when i >= STATIONS (else already included)
        float sd = 0.f;
        const bool hasd = (i >= STATIONS);
        if (hasd) {
            const float* krow = kbase + (size_t)i * QKVLD;
            float part = qa * krow[lane] + qb * krow[lane + 32];
#pragma unroll
            for (int o = 16; o > 0; o >>= 1) part += __shfl_xor_sync(0xffffffffu, part, o);
            sd = part + rrow[i];
        }

        // softmax over 128 (+1) entries, scale = 1/sqrt(64)
        const float sc = 0.125f;
        float t[4];
        float m = hasd ? sd * sc : -1e30f;
#pragma unroll
        for (int r = 0; r < 4; r++) { t[r] = s[r] * sc; m = fmaxf(m, t[r]); }
#pragma unroll
        for (int o = 16; o > 0; o >>= 1) m = fmaxf(m, __shfl_xor_sync(0xffffffffu, m, o));
        float e[4], sum = 0.f;
#pragma unroll
        for (int r = 0; r < 4; r++) { e[r] = __expf(t[r] - m); sum += e[r]; }
#pragma unroll
        for (int o = 16; o > 0; o >>= 1) sum += __shfl_xor_sync(0xffffffffu, sum, o);
        float ed = hasd ? __expf(sd * sc - m) : 0.f;
        sum += ed;
        float inv = 1.f / sum;
#pragma unroll
        for (int r = 0; r < 4; r++) P[qq][r] = e[r] * inv;
        PD[qq] = ed * inv;
    }
    __syncthreads();

    // Phase 2: V stations: sm[j*65 + d] = v[b,j,h,d]
    for (int idx = tid; idx < STATIONS * 64; idx += 256) {
        int j = idx >> 6, d = idx & 63;
        sm[j * 65 + d] = vbase[(size_t)j * QKVLD + d];
    }
    __syncthreads();

#pragma unroll
    for (int qq = 0; qq < 8; qq++) {
        const int i = i0 + qq;
        float c0 = 0.f, c1 = 0.f;
#pragma unroll
        for (int r = 0; r < 4; r++) {
#pragma unroll
            for (int jj = 0; jj < 32; jj++) {
                float pj = __shfl_sync(0xffffffffu, P[qq][r], jj);
                int j = r * 32 + jj;
                c0 += pj * sm[j * 65 + lane];
                c1 += pj * sm[j * 65 + lane + 32];
            }
        }
        if (i >= STATIONS) {
            const float* vrow = vbase + (size_t)i * QKVLD;
            c0 += PD[qq] * vrow[lane];
            c1 += PD[qq] * vrow[lane + 32];
        }
        float* crow = g_ctx + (((size_t)b * SEQ + i) * NH + h) * 64;
        crow[lane]      = c0;
        crow[lane + 32] = c1;
    }
}

// ---------------------------------------------------------------------------
// bias + residual + LayerNorm, one block (256 thr) per row of 512.
// ---------------------------------------------------------------------------
__device__ __forceinline__ float block_sum512(float v, float* red)
{
    const int lane = threadIdx.x & 31, w = threadIdx.x >> 5;
#pragma unroll
    for (int o = 16; o > 0; o >>= 1) v += __shfl_xor_sync(0xffffffffu, v, o);
    if (lane == 0) red[w] = v;
    __syncthreads();
    if (threadIdx.x == 0) {
        float tot = 0.f;
#pragma unroll
        for (int k = 0; k < 8; k++) tot += red[k];
        red[0] = tot;
    }
    __syncthreads();
    float result = red[0];
    __syncthreads();
    return result;
}

__global__ __launch_bounds__(256) void ln_kernel(const float* __restrict__ resid,
                                                 const float* __restrict__ fcb,
                                                 const float* __restrict__ g,
                                                 const float* __restrict__ bb,
                                                 float* __restrict__ out)
{
    __shared__ float red[8];
    const int row = blockIdx.x;
    const int tid = threadIdx.x;
    const float* yr = g_y + (size_t)row * DMODEL;
    const float* rr = resid + (size_t)row * DMODEL;

    float x0 = yr[tid]       + fcb[tid]       + rr[tid];
    float x1 = yr[tid + 256] + fcb[tid + 256] + rr[tid + 256];

    float mu = block_sum512(x0 + x1, red) * (1.f / 512.f);
    float d0 = x0 - mu, d1 = x1 - mu;
    float var = block_sum512(d0 * d0 + d1 * d1, red) * (1.f / 512.f);
    float inv = rsqrtf(var + 1e-6f);

    out[(size_t)row * DMODEL + tid]       = d0 * inv * g[tid]       + bb[tid];
    out[(size_t)row * DMODEL + tid + 256] = d1 * inv * g[tid + 256] + bb[tid + 256];
}

// ---------------------------------------------------------------------------
extern "C" void kernel_launch(void* const* d_in, const int* in_sizes, int n_in,
                              void* d_out, int out_size)
{
    const float* hs  = (const float*)d_in[0];
    const float* rpe = (const float*)d_in[1];
    const float* Wq  = (const float*)d_in[2];
    const float* Wk  = (const float*)d_in[3];
    const float* Wv  = (const float*)d_in[4];
    const float* fcw = (const float*)d_in[5];
    const float* fcb = (const float*)d_in[6];
    const float* lng = (const float*)d_in[7];
    const float* lnb = (const float*)d_in[8];
    float* out = (float*)d_out;

    sgemm_qkv<<<dim3(ROWS / 128, QKVLD / 128), 256>>>(hs, Wq, Wk, Wv);
    attn_kernel<<<dim3(SEQ / 64, NH, BSZ), 256>>>(rpe);
    sgemm_fc<<<dim3(ROWS / 128, DMODEL / 128), 256>>>(fcw);
    ln_kernel<<<ROWS, 256>>>(hs, fcb, lng, lnb, out);
}

// round 3
// speedup vs baseline: 1.4663x; 1.4663x over previous
#include <cuda_runtime.h>
#include <cuda_bf16.h>
#include <cstdint>

// Problem constants
#define BSZ 8
#define SEQ 1024
#define DMODEL 512
#define NH 8
#define DK 64
#define STATIONS 128
#define ROWS (BSZ * SEQ)          // 8192
#define QKVLD 1536                // q|k|v concatenated per row

// Scratch (static device globals; no runtime allocation)
__device__ float g_qkv[ROWS * QKVLD];     // [8192][1536] = q|k|v
__device__ float g_ctx[ROWS * DMODEL];    // attention output, [b,i,h*64+d]
__device__ float g_y[ROWS * DMODEL];      // fc output pre-LN

// ---------------------------------------------------------------------------
// TF32 tensor-core GEMM: C[m0:+128, c0:+128] = A[m0:,0:512] @ B[n0:+128,0:512]^T
// BM=BN=128, BK=16, 256 threads (8 warps, 4x2), warp tile 32x64 via m16n8k8.
// fp32 -> tf32 conversion at the global->shared stage. Smem stride 20 floats:
// conflict-free fragment LDS + 16B-aligned vector stores.
// ---------------------------------------------------------------------------
#define SST 20   // smem row stride (floats)

__device__ __forceinline__ uint32_t f2tf(float x) {
    uint32_t u;
    asm("cvt.rna.tf32.f32 %0, %1;" : "=r"(u) : "f"(x));
    return u;
}

__device__ __forceinline__ void mma_tf32(float* c, const uint32_t* a, const uint32_t* b) {
    asm("mma.sync.aligned.m16n8k8.row.col.f32.tf32.tf32.f32 "
        "{%0,%1,%2,%3},{%4,%5,%6,%7},{%8,%9},{%0,%1,%2,%3};"
        : "+f"(c[0]), "+f"(c[1]), "+f"(c[2]), "+f"(c[3])
        : "r"(a[0]), "r"(a[1]), "r"(a[2]), "r"(a[3]), "r"(b[0]), "r"(b[1]));
}

__device__ __forceinline__ void gemm_tc(const float* __restrict__ A,
                                        const float* __restrict__ B,
                                        float* __restrict__ C,
                                        int m0, int n0, int c0, int ldc)
{
    __shared__ uint32_t As[2][128 * SST];
    __shared__ uint32_t Bs[2][128 * SST];

    const int tid  = threadIdx.x;
    const int lane = tid & 31;
    const int wid  = tid >> 5;
    const int wm   = (wid & 3) * 32;   // warp m offset in tile
    const int wn   = (wid >> 2) * 64;  // warp n offset in tile

    // global-load element ids: e -> row = e>>2, k4 = (e&3)*4
    const int e0 = tid, e1 = tid + 256;
    const float* Ag = A + (size_t)m0 * 512;
    const float* Bg = B + (size_t)n0 * 512;

    float acc[2][8][4];
#pragma unroll
    for (int i = 0; i < 2; i++)
#pragma unroll
        for (int j = 0; j < 8; j++)
#pragma unroll
            for (int r = 0; r < 4; r++) acc[i][j][r] = 0.f;

    float4 av0, av1, bv0, bv1;

    auto ldg_tile = [&](int kt) {
        av0 = *(const float4*)(Ag + (size_t)(e0 >> 2) * 512 + (e0 & 3) * 4 + kt);
        av1 = *(const float4*)(Ag + (size_t)(e1 >> 2) * 512 + (e1 & 3) * 4 + kt);
        bv0 = *(const float4*)(Bg + (size_t)(e0 >> 2) * 512 + (e0 & 3) * 4 + kt);
        bv1 = *(const float4*)(Bg + (size_t)(e1 >> 2) * 512 + (e1 & 3) * 4 + kt);
    };
    auto sts_tile = [&](int buf) {
        uint32_t* pa0 = &As[buf][(e0 >> 2) * SST + (e0 & 3) * 4];
        uint32_t* pa1 = &As[buf][(e1 >> 2) * SST + (e1 & 3) * 4];
        uint32_t* pb0 = &Bs[buf][(e0 >> 2) * SST + (e0 & 3) * 4];
        uint32_t* pb1 = &Bs[buf][(e1 >> 2) * SST + (e1 & 3) * 4];
        *(uint4*)pa0 = make_uint4(f2tf(av0.x), f2tf(av0.y), f2tf(av0.z), f2tf(av0.w));
        *(uint4*)pa1 = make_uint4(f2tf(av1.x), f2tf(av1.y), f2tf(av1.z), f2tf(av1.w));
        *(uint4*)pb0 = make_uint4(f2tf(bv0.x), f2tf(bv0.y), f2tf(bv0.z), f2tf(bv0.w));
        *(uint4*)pb1 = make_uint4(f2tf(bv1.x), f2tf(bv1.y), f2tf(bv1.z), f2tf(bv1.w));
    };
    auto compute = [&](int buf) {
        const uint32_t* SA = As[buf];
        const uint32_t* SB = Bs[buf];
#pragma unroll
        for (int kk = 0; kk < 16; kk += 8) {
            uint32_t a[2][4];
#pragma unroll
            for (int mt = 0; mt < 2; mt++) {
                int r = wm + mt * 16 + (lane >> 2);
                int c = kk + (lane & 3);
                a[mt][0] = SA[r * SST + c];
                a[mt][1] = SA[(r + 8) * SST + c];
                a[mt][2] = SA[r * SST + c + 4];
                a[mt][3] = SA[(r + 8) * SST + c + 4];
            }
            uint32_t b[8][2];
#pragma unroll
            for (int nt = 0; nt < 8; nt++) {
                int n = wn + nt * 8 + (lane >> 2);
                b[nt][0] = SB[n * SST + kk + (lane & 3)];
                b[nt][1] = SB[n * SST + kk + 4 + (lane & 3)];
            }
#pragma unroll
            for (int mt = 0; mt < 2; mt++)
#pragma unroll
                for (int nt = 0; nt < 8; nt++)
                    mma_tf32(acc[mt][nt], a[mt], b[nt]);
        }
    };

    // pipeline
    ldg_tile(0);
    sts_tile(0);
    __syncthreads();
    int buf = 0;
#pragma unroll 1
    for (int kt = 16; kt < 512; kt += 16) {
        ldg_tile(kt);
        compute(buf);
        sts_tile(buf ^ 1);
        __syncthreads();
        buf ^= 1;
    }
    compute(buf);

    // epilogue: fp32 stores, float2 per fragment half-row
#pragma unroll
    for (int mt = 0; mt < 2; mt++) {
#pragma unroll
        for (int nt = 0; nt < 8; nt++) {
            int row = m0 + wm + mt * 16 + (lane >> 2);
            int col = c0 + wn + nt * 8 + (lane & 3) * 2;
            *(float2*)(C + (size_t)row * ldc + col) =
                make_float2(acc[mt][nt][0], acc[mt][nt][1]);
            *(float2*)(C + (size_t)(row + 8) * ldc + col) =
                make_float2(acc[mt][nt][2], acc[mt][nt][3]);
        }
    }
}

// QKV: g_qkv = hs @ [Wq|Wk|Wv]^T
__global__ __launch_bounds__(256, 2) void qkv_tc(const float* __restrict__ hs,
                                                 const float* __restrict__ Wq,
                                                 const float* __restrict__ Wk,
                                                 const float* __restrict__ Wv)
{
    int m0 = blockIdx.x * 128;
    int gcol = blockIdx.y * 128;
    const float* B = (gcol < 512) ? Wq : (gcol < 1024 ? Wk : Wv);
    gemm_tc(hs, B, g_qkv, m0, gcol & 511, gcol, QKVLD);
}

// FC: g_y = g_ctx @ fc_w^T
__global__ __launch_bounds__(256, 2) void fc_tc(const float* __restrict__ fcw)
{
    gemm_tc(g_ctx, fcw, g_y, blockIdx.x * 128, blockIdx.y * 128, blockIdx.y * 128, DMODEL);
}

// ---------------------------------------------------------------------------
// Sparse star attention (unchanged from R1). Block = (qtile, h, b), 256 thr.
// ---------------------------------------------------------------------------
__global__ __launch_bounds__(256) void attn_kernel(const float* __restrict__ rpe)
{
    __shared__ float sm[128 * 65];

    const int b = blockIdx.z, h = blockIdx.y, qt = blockIdx.x;
    const int tid = threadIdx.x, lane = tid & 31, w = tid >> 5;

    const float* qbase = g_qkv + (size_t)b * SEQ * QKVLD + h * 64;
    const float* kbase = qbase + 512;
    const float* vbase = qbase + 1024;

    for (int idx = tid; idx < STATIONS * 64; idx += 256) {
        int j = idx >> 6, d = idx & 63;
        sm[d * 129 + j] = kbase[(size_t)j * QKVLD + d];
    }
    __syncthreads();

    float P[8][4];
    float PD[8];
    const int i0 = qt * 64 + w * 8;

#pragma unroll
    for (int qq = 0; qq < 8; qq++) {
        const int i = i0 + qq;
        const float* qrow = qbase + (size_t)i * QKVLD;
        const float qa = qrow[lane], qb = qrow[lane + 32];

        float s[4] = {0.f, 0.f, 0.f, 0.f};
#pragma unroll
        for (int d = 0; d < 64; d++) {
            float qd = __shfl_sync(0xffffffffu, (d < 32 ? qa : qb), d & 31);
            const float* Kd = &sm[d * 129];
            s[0] += qd * Kd[lane];
            s[1] += qd * Kd[lane + 32];
            s[2] += qd * Kd[lane + 64];
            s[3] += qd * Kd[lane + 96];
        }
        const float* rrow = rpe + (((size_t)(b * NH + h) * SEQ + i) * SEQ);
        s[0] += rrow[lane];      s[1] += rrow[lane + 32];
        s[2] += rrow[lane + 64]; s[3] += rrow[lane + 96];

        float sd = 0.f;
        const bool hasd = (i >= STATIONS);
        if (hasd) {
            const float* krow = kbase + (size_t)i * QKVLD;
            float part = qa * krow[lane] + qb * krow[lane + 32];
#pragma unroll
            for (int o = 16; o > 0; o >>= 1) part += __shfl_xor_sync(0xffffffffu, part, o);
            sd = part + rrow[i];
        }

        const float sc = 0.125f;
        float t[4];
        float m = hasd ? sd * sc : -1e30f;
#pragma unroll
        for (int r = 0; r < 4; r++) { t[r] = s[r] * sc; m = fmaxf(m, t[r]); }
#pragma unroll
        for (int o = 16; o > 0; o >>= 1) m = fmaxf(m, __shfl_xor_sync(0xffffffffu, m, o));
        float e[4], sum = 0.f;
#pragma unroll
        for (int r = 0; r < 4; r++) { e[r] = __expf(t[r] - m); sum += e[r]; }
#pragma unroll
        for (int o = 16; o > 0; o >>= 1) sum += __shfl_xor_sync(0xffffffffu, sum, o);
        float ed = hasd ? __expf(sd * sc - m) : 0.f;
        sum += ed;
        float inv = 1.f / sum;
#pragma unroll
        for (int r = 0; r < 4; r++) P[qq][r] = e[r] * inv;
        PD[qq] = ed * inv;
    }
    __syncthreads();

    for (int idx = tid; idx < STATIONS * 64; idx += 256) {
        int j = idx >> 6, d = idx & 63;
        sm[j * 65 + d] = vbase[(size_t)j * QKVLD + d];
    }
    __syncthreads();

#pragma unroll
    for (int qq = 0; qq < 8; qq++) {
        const int i = i0 + qq;
        float c0 = 0.f, c1 = 0.f;
#pragma unroll
        for (int r = 0; r < 4; r++) {
#pragma unroll
            for (int jj = 0; jj < 32; jj++) {
                float pj = __shfl_sync(0xffffffffu, P[qq][r], jj);
                int j = r * 32 + jj;
                c0 += pj * sm[j * 65 + lane];
                c1 += pj * sm[j * 65 + lane + 32];
            }
        }
        if (i >= STATIONS) {
            const float* vrow = vbase + (size_t)i * QKVLD;
            c0 += PD[qq] * vrow[lane];
            c1 += PD[qq] * vrow[lane + 32];
        }
        float* crow = g_ctx + (((size_t)b * SEQ + i) * NH + h) * 64;
        crow[lane]      = c0;
        crow[lane + 32] = c1;
    }
}

// ---------------------------------------------------------------------------
// bias + residual + LayerNorm, one block (256 thr) per row of 512.
// ---------------------------------------------------------------------------
__device__ __forceinline__ float block_sum512(float v, float* red)
{
    const int lane = threadIdx.x & 31, w = threadIdx.x >> 5;
#pragma unroll
    for (int o = 16; o > 0; o >>= 1) v += __shfl_xor_sync(0xffffffffu, v, o);
    if (lane == 0) red[w] = v;
    __syncthreads();
    if (threadIdx.x == 0) {
        float tot = 0.f;
#pragma unroll
        for (int k = 0; k < 8; k++) tot += red[k];
        red[0] = tot;
    }
    __syncthreads();
    float result = red[0];
    __syncthreads();
    return result;
}

__global__ __launch_bounds__(256) void ln_kernel(const float* __restrict__ resid,
                                                 const float* __restrict__ fcb,
                                                 const float* __restrict__ g,
                                                 const float* __restrict__ bb,
                                                 float* __restrict__ out)
{
    __shared__ float red[8];
    const int row = blockIdx.x;
    const int tid = threadIdx.x;
    const float* yr = g_y + (size_t)row * DMODEL;
    const float* rr = resid + (size_t)row * DMODEL;

    float x0 = yr[tid]       + fcb[tid]       + rr[tid];
    float x1 = yr[tid + 256] + fcb[tid + 256] + rr[tid + 256];

    float mu = block_sum512(x0 + x1, red) * (1.f / 512.f);
    float d0 = x0 - mu, d1 = x1 - mu;
    float var = block_sum512(d0 * d0 + d1 * d1, red) * (1.f / 512.f);
    float inv = rsqrtf(var + 1e-6f);

    out[(size_t)row * DMODEL + tid]       = d0 * inv * g[tid]       + bb[tid];
    out[(size_t)row * DMODEL + tid + 256] = d1 * inv * g[tid + 256] + bb[tid + 256];
}

// ---------------------------------------------------------------------------
extern "C" void kernel_launch(void* const* d_in, const int* in_sizes, int n_in,
                              void* d_out, int out_size)
{
    const float* hs  = (const float*)d_in[0];
    const float* rpe = (const float*)d_in[1];
    const float* Wq  = (const float*)d_in[2];
    const float* Wk  = (const float*)d_in[3];
    const float* Wv  = (const float*)d_in[4];
    const float* fcw = (const float*)d_in[5];
    const float* fcb = (const float*)d_in[6];
    const float* lng = (const float*)d_in[7];
    const float* lnb = (const float*)d_in[8];
    float* out = (float*)d_out;

    qkv_tc<<<dim3(ROWS / 128, QKVLD / 128), 256>>>(hs, Wq, Wk, Wv);
    attn_kernel<<<dim3(SEQ / 64, NH, BSZ), 256>>>(rpe);
    fc_tc<<<dim3(ROWS / 128, DMODEL / 128), 256>>>(fcw);
    ln_kernel<<<ROWS, 256>>>(hs, fcb, lng, lnb, out);
}

// round 8
// speedup vs baseline: 2.5063x; 1.7093x over previous
#include <cuda_runtime.h>
#include <cuda_bf16.h>
#include <cstdint>

// Problem constants
#define BSZ 8
#define SEQ 1024
#define DM 512
#define NH 8
#define DK 64
#define STATIONS 128
#define ROWS (BSZ * SEQ)          // 8192
#define QKVLD 1536

// Scratch (static device globals)
__device__ float g_qkv[ROWS * QKVLD];           // fp32 q|k|v
__device__ float g_y[ROWS * DM];                // fc output pre-LN
__device__ __nv_bfloat16 g_hsb[ROWS * DM];      // hs bf16
__device__ __nv_bfloat16 g_wb[QKVLD * DM];      // Wq|Wk|Wv stacked bf16
__device__ __nv_bfloat16 g_fwb[DM * DM];        // fc_w bf16
__device__ __nv_bfloat16 g_ctxb[ROWS * DM];     // attention ctx bf16

// ---------------------------------------------------------------------------
// helpers
// ---------------------------------------------------------------------------
__device__ __forceinline__ uint32_t smem_u32(const void* p) {
    uint32_t a;
    asm("{ .reg .u64 t; cvta.to.shared.u64 t, %1; cvt.u32.u64 %0, t; }" : "=r"(a) : "l"(p));
    return a;
}
#define SMEM_SWZ(x) ((x) ^ (((x) >> 3) & 0x70))

__device__ __forceinline__ void ldmx4(uint32_t* r, uint32_t addr) {
    asm volatile("ldmatrix.sync.aligned.m8n8.x4.shared.b16 {%0,%1,%2,%3}, [%4];"
        : "=r"(r[0]), "=r"(r[1]), "=r"(r[2]), "=r"(r[3]) : "r"(addr));
}
__device__ __forceinline__ void mma_bf16(float* c, const uint32_t* a, uint32_t b0, uint32_t b1) {
    asm volatile("mma.sync.aligned.m16n8k16.row.col.f32.bf16.bf16.f32 "
        "{%0,%1,%2,%3},{%4,%5,%6,%7},{%8,%9},{%0,%1,%2,%3};"
        : "+f"(c[0]), "+f"(c[1]), "+f"(c[2]), "+f"(c[3])
        : "r"(a[0]), "r"(a[1]), "r"(a[2]), "r"(a[3]), "r"(b0), "r"(b1));
}

// ---------------------------------------------------------------------------
// bf16 HMMA GEMM: C[m0:+128, c0:+128] = A[m0:,0:512] @ B[0:+128,0:512]^T
// (unchanged from R5)
// ---------------------------------------------------------------------------
#define ABYTES 16384                       // 128 rows x 128B
#define GEMM_SMEM (4 * ABYTES)             // 2 buffers x (A+B) = 64KB

__device__ __forceinline__ void gemm128_bf16(const __nv_bfloat16* __restrict__ Abase,
                                             const __nv_bfloat16* __restrict__ Bbase,
                                             float* __restrict__ C,
                                             int m0, int c0, int ldc)
{
    extern __shared__ char smem[];
    const uint32_t sb = smem_u32(smem);
    const int tid = threadIdx.x, lane = tid & 31, wid = tid >> 5;
    const int wm = (wid & 3) * 32;
    const int wn = (wid >> 2) * 64;

    const uint4* Ag = (const uint4*)(Abase + (size_t)m0 * DM);
    const uint4* Bg = (const uint4*)Bbase;

    float acc[2][8][4];
#pragma unroll
    for (int i = 0; i < 2; i++)
#pragma unroll
        for (int j = 0; j < 8; j++)
#pragma unroll
            for (int r = 0; r < 4; r++) acc[i][j][r] = 0.f;

    uint4 ra[4], rb[4];
    auto ldg_chunk = [&](int c) {
#pragma unroll
        for (int it = 0; it < 4; it++) {
            int idx = tid + it * 256;
            int row = idx >> 3, seg = idx & 7;
            ra[it] = Ag[row * 64 + c * 8 + seg];
            rb[it] = Bg[row * 64 + c * 8 + seg];
        }
    };
    auto sts_chunk = [&](int buf) {
        char* ab = smem + buf * 2 * ABYTES;
        char* bb = ab + ABYTES;
#pragma unroll
        for (int it = 0; it < 4; it++) {
            int idx = tid + it * 256;
            int row = idx >> 3, seg = idx & 7;
            *(uint4*)(ab + SMEM_SWZ(row * 128 + seg * 16)) = ra[it];
            *(uint4*)(bb + SMEM_SWZ(row * 128 + seg * 16)) = rb[it];
        }
    };
    auto compute = [&](int buf) {
        const uint32_t a_base = sb + buf * 2 * ABYTES;
        const uint32_t b_base = a_base + ABYTES;
        const int lr = lane & 15;
        const int lc = (lane >> 4) << 4;
#pragma unroll
        for (int ks = 0; ks < 4; ks++) {
            const int kb = ks * 32 + lc;
            uint32_t a[2][4];
#pragma unroll
            for (int mt = 0; mt < 2; mt++) {
                int row = wm + mt * 16 + lr;
                ldmx4(a[mt], a_base + SMEM_SWZ(row * 128 + kb));
            }
#pragma unroll
            for (int ng = 0; ng < 4; ng++) {
                uint32_t bf[4];
                int row = wn + ng * 16 + lr;
                ldmx4(bf, b_base + SMEM_SWZ(row * 128 + kb));
#pragma unroll
                for (int mt = 0; mt < 2; mt++) {
                    mma_bf16(acc[mt][ng * 2],     a[mt], bf[0], bf[2]);
                    mma_bf16(acc[mt][ng * 2 + 1], a[mt], bf[1], bf[3]);
                }
            }
        }
    };

    ldg_chunk(0);
    sts_chunk(0);
    __syncthreads();
    int buf = 0;
#pragma unroll 1
    for (int c = 1; c < 8; c++) {
        ldg_chunk(c);
        compute(buf);
        sts_chunk(buf ^ 1);
        __syncthreads();
        buf ^= 1;
    }
    compute(buf);

#pragma unroll
    for (int mt = 0; mt < 2; mt++) {
#pragma unroll
        for (int nt = 0; nt < 8; nt++) {
            int row = m0 + wm + mt * 16 + (lane >> 2);
            int col = c0 + wn + nt * 8 + (lane & 3) * 2;
            *(float2*)(C + (size_t)row * ldc + col) =
                make_float2(acc[mt][nt][0], acc[mt][nt][1]);
            *(float2*)(C + (size_t)(row + 8) * ldc + col) =
                make_float2(acc[mt][nt][2], acc[mt][nt][3]);
        }
    }
}

__global__ __launch_bounds__(256) void qkv_bf16()
{
    int m0 = blockIdx.x * 128;
    int gcol = blockIdx.y * 128;
    gemm128_bf16(g_hsb, g_wb + (size_t)gcol * DM, g_qkv, m0, gcol, QKVLD);
}

__global__ __launch_bounds__(256) void fc_bf16()
{
    int m0 = blockIdx.x * 128;
    int n0 = blockIdx.y * 128;
    gemm128_bf16(g_ctxb, g_fwb + (size_t)n0 * DM, g_y, m0, n0, DM);
}

// ---------------------------------------------------------------------------
// fp32 -> bf16 pre-convert (hs, Wq, Wk, Wv stacked, fc_w). vec4 granularity.
// ---------------------------------------------------------------------------
#define HS4   1048576u   // 8192*512/4
#define W4    65536u     // 512*512/4
__global__ __launch_bounds__(256) void conv_bf16(const float* __restrict__ hs,
                                                 const float* __restrict__ Wq,
                                                 const float* __restrict__ Wk,
                                                 const float* __restrict__ Wv,
                                                 const float* __restrict__ fcw)
{
    uint32_t v = blockIdx.x * 256 + threadIdx.x;
    const float4* src;
    __nv_bfloat16* dst;
    if (v < HS4)                  { src = (const float4*)hs  + v;                 dst = g_hsb + (size_t)v * 4; }
    else if (v < HS4 + W4)        { src = (const float4*)Wq  + (v - HS4);         dst = g_wb  + (size_t)(v - HS4) * 4; }
    else if (v < HS4 + 2 * W4)    { src = (const float4*)Wk  + (v - HS4 - W4);    dst = g_wb  + (size_t)(v - HS4 - W4) * 4 + 262144; }
    else if (v < HS4 + 3 * W4)    { src = (const float4*)Wv  + (v - HS4 - 2*W4);  dst = g_wb  + (size_t)(v - HS4 - 2*W4) * 4 + 524288; }
    else                          { src = (const float4*)fcw + (v - HS4 - 3*W4);  dst = g_fwb + (size_t)(v - HS4 - 3*W4) * 4; }
    float4 f = *src;
    __nv_bfloat162 lo = __floats2bfloat162_rn(f.x, f.y);
    __nv_bfloat162 hi = __floats2bfloat162_rn(f.z, f.w);
    *(uint2*)dst = make_uint2(*(uint32_t*)&lo, *(uint32_t*)&hi);
}
#define CONV_BLOCKS ((HS4 + 4 * W4) / 256)

// ---------------------------------------------------------------------------
// Sparse star attention, hybrid: S = Q@K^T via HMMA (same pattern as GEMM),
// softmax / rpe / diagonal / PV unchanged from the R3-validated structure.
// Block = (qtile of 64 queries, h, b), 256 threads (8 warps).
// Smem phases (aliased union, fenced by __syncthreads):
//   [stage smQ(8KB)+smK(16KB)] -> MMA -> [Ssm 64x132 f32] -> softmax ->
//   [smV 128x65 f32] -> PV
// ---------------------------------------------------------------------------
__global__ __launch_bounds__(256) void attn_kernel(const float* __restrict__ rpe)
{
    __shared__ float sm[8448];          // 33.8KB, aliased across phases
    char* smc = (char*)sm;              // bf16 staging base
    const uint32_t sQ = smem_u32(smc);          // Q tile bytes [64][128B]
    const uint32_t sK = sQ + 8192;              // K tile bytes [128][128B]

    const int b = blockIdx.z, h = blockIdx.y, qt = blockIdx.x;
    const int tid = threadIdx.x, lane = tid & 31, w = tid >> 5;

    const float* qbase = g_qkv + (size_t)b * SEQ * QKVLD + h * 64;
    const float* kbase = qbase + 512;
    const float* vbase = qbase + 1024;
    const int i0q = qt * 64;

    // ---- Phase 1: stage Q (64x64) and K stations (128x64) as bf16, SW128 ----
#pragma unroll
    for (int t = 0; t < 4; t++) {                  // Q: 1024 float4
        int idx4 = tid + t * 256;
        int row = idx4 >> 4, dd = (idx4 & 15) * 4;
        float4 f = *(const float4*)(qbase + (size_t)(i0q + row) * QKVLD + dd);
        __nv_bfloat162 lo = __floats2bfloat162_rn(f.x, f.y);
        __nv_bfloat162 hi = __floats2bfloat162_rn(f.z, f.w);
        *(uint2*)(smc + SMEM_SWZ(row * 128 + dd * 2)) =
            make_uint2(*(uint32_t*)&lo, *(uint32_t*)&hi);
    }
#pragma unroll
    for (int t = 0; t < 8; t++) {                  // K: 2048 float4
        int idx4 = tid + t * 256;
        int row = idx4 >> 4, dd = (idx4 & 15) * 4;
        float4 f = *(const float4*)(kbase + (size_t)row * QKVLD + dd);
        __nv_bfloat162 lo = __floats2bfloat162_rn(f.x, f.y);
        __nv_bfloat162 hi = __floats2bfloat162_rn(f.z, f.w);
        *(uint2*)(smc + 8192 + SMEM_SWZ(row * 128 + dd * 2)) =
            make_uint2(*(uint32_t*)&lo, *(uint32_t*)&hi);
    }
    __syncthreads();

    // ---- Phase 2: S[64x128] = Q @ K^T. Warp grid 4x2: m-tile 16, n 64. ----
    const int wm16 = (w & 3) * 16;
    const int wn64 = (w >> 2) * 64;
    float acc[8][4];
#pragma unroll
    for (int j = 0; j < 8; j++)
#pragma unroll
        for (int r = 0; r < 4; r++) acc[j][r] = 0.f;
    {
        const int lr = lane & 15;
        const int lc = (lane >> 4) << 4;
#pragma unroll
        for (int ks = 0; ks < 4; ks++) {
            const int kb = ks * 32 + lc;
            uint32_t a4[4];
            ldmx4(a4, sQ + SMEM_SWZ((wm16 + lr) * 128 + kb));
#pragma unroll
            for (int ng = 0; ng < 4; ng++) {
                uint32_t bf[4];
                ldmx4(bf, sK + SMEM_SWZ((wn64 + ng * 16 + lr) * 128 + kb));
                mma_bf16(acc[ng * 2],     a4, bf[0], bf[2]);
                mma_bf16(acc[ng * 2 + 1], a4, bf[1], bf[3]);
            }
        }
    }
    __syncthreads();   // done reading smQ/smK; Ssm aliases them

    // ---- Phase 3: epilogue S -> Ssm[64][132] fp32 ----
    {
        const int r = wm16 + (lane >> 2);
        const int cb = wn64 + (lane & 3) * 2;
#pragma unroll
        for (int nt = 0; nt < 8; nt++) {
            int c = cb + nt * 8;
            *(float2*)(&sm[r * 132 + c])       = make_float2(acc[nt][0], acc[nt][1]);
            *(float2*)(&sm[(r + 8) * 132 + c]) = make_float2(acc[nt][2], acc[nt][3]);
        }
    }
    __syncthreads();

    // ---- Phase 4: softmax (structure unchanged from R3; qk read from Ssm) ----
    float P[8][4];
    float PD[8];
    const int i0 = i0q + w * 8;

#pragma unroll
    for (int qq = 0; qq < 8; qq++) {
        const int i = i0 + qq;
        const int qrowl = w * 8 + qq;            // local row in Ssm
        const float* qrow = qbase + (size_t)i * QKVLD;
        const float qa = qrow[lane], qb = qrow[lane + 32];

        float s[4];
        s[0] = sm[qrowl * 132 + lane];
        s[1] = sm[qrowl * 132 + lane + 32];
        s[2] = sm[qrowl * 132 + lane + 64];
        s[3] = sm[qrowl * 132 + lane + 96];

        const float* rrow = rpe + (((size_t)(b * NH + h) * SEQ + i) * SEQ);
        s[0] += rrow[lane];      s[1] += rrow[lane + 32];
        s[2] += rrow[lane + 64]; s[3] += rrow[lane + 96];

        float sd = 0.f;
        const bool hasd = (i >= STATIONS);
        if (hasd) {
            const float* krow = kbase + (size_t)i * QKVLD;
            float part = qa * krow[lane] + qb * krow[lane + 32];
#pragma unroll
            for (int o = 16; o > 0; o >>= 1) part += __shfl_xor_sync(0xffffffffu, part, o);
            sd = part + rrow[i];
        }

        const float sc = 0.125f;
        float t[4];
        float m = hasd ? sd * sc : -1e30f;
#pragma unroll
        for (int r = 0; r < 4; r++) { t[r] = s[r] * sc; m = fmaxf(m, t[r]); }
#pragma unroll
        for (int o = 16; o > 0; o >>= 1) m = fmaxf(m, __shfl_xor_sync(0xffffffffu, m, o));
        float e[4], sum = 0.f;
#pragma unroll
        for (int r = 0; r < 4; r++) { e[r] = __expf(t[r] - m); sum += e[r]; }
#pragma unroll
        for (int o = 16; o > 0; o >>= 1) sum += __shfl_xor_sync(0xffffffffu, sum, o);
        float ed = hasd ? __expf(sd * sc - m) : 0.f;
        sum += ed;
        float inv = 1.f / sum;
#pragma unroll
        for (int r = 0; r < 4; r++) P[qq][r] = e[r] * inv;
        PD[qq] = ed * inv;
    }
    __syncthreads();   // done reading Ssm; smV aliases it

    // ---- Phase 5: stage V, then PV (unchanged from R3/R5) ----
    for (int idx = tid; idx < STATIONS * 64; idx += 256) {
        int j = idx >> 6, d = idx & 63;
        sm[j * 65 + d] = vbase[(size_t)j * QKVLD + d];
    }
    __syncthreads();

#pragma unroll
    for (int qq = 0; qq < 8; qq++) {
        const int i = i0 + qq;
        float c0 = 0.f, c1 = 0.f;
#pragma unroll
        for (int r = 0; r < 4; r++) {
#pragma unroll
            for (int jj = 0; jj < 32; jj++) {
                float pj = __shfl_sync(0xffffffffu, P[qq][r], jj);
                int j = r * 32 + jj;
                c0 += pj * sm[j * 65 + lane];
                c1 += pj * sm[j * 65 + lane + 32];
            }
        }
        if (i >= STATIONS) {
            const float* vrow = vbase + (size_t)i * QKVLD;
            c0 += PD[qq] * vrow[lane];
            c1 += PD[qq] * vrow[lane + 32];
        }
        __nv_bfloat16* crow = g_ctxb + (((size_t)b * SEQ + i) * NH + h) * 64;
        crow[lane]      = __float2bfloat16_rn(c0);
        crow[lane + 32] = __float2bfloat16_rn(c1);
    }
}

// ---------------------------------------------------------------------------
// bias + residual + LayerNorm: one warp per row, shuffle-only reductions.
// ---------------------------------------------------------------------------
__global__ __launch_bounds__(256) void ln2_kernel(const float* __restrict__ resid,
                                                  const float* __restrict__ fcb,
                                                  const float* __restrict__ g,
                                                  const float* __restrict__ bb,
                                                  float* __restrict__ out)
{
    const int lane = threadIdx.x & 31;
    const int row = blockIdx.x * 8 + (threadIdx.x >> 5);
    const float4* y4 = (const float4*)(g_y + (size_t)row * DM);
    const float4* r4 = (const float4*)(resid + (size_t)row * DM);
    const float4* f4 = (const float4*)fcb;
    const float4* g4 = (const float4*)g;
    const float4* b4 = (const float4*)bb;
    float4* o4 = (float4*)(out + (size_t)row * DM);

    float4 x[4];
    float s = 0.f;
#pragma unroll
    for (int k = 0; k < 4; k++) {
        int ci = lane + k * 32;
        float4 a = y4[ci], rr = r4[ci], ff = f4[ci];
        x[k] = make_float4(a.x + rr.x + ff.x, a.y + rr.y + ff.y,
                           a.z + rr.z + ff.z, a.w + rr.w + ff.w);
        s += x[k].x + x[k].y + x[k].z + x[k].w;
    }
#pragma unroll
    for (int o = 16; o > 0; o >>= 1) s += __shfl_xor_sync(0xffffffffu, s, o);
    const float mu = s * (1.f / 512.f);

    float v = 0.f;
#pragma unroll
    for (int k = 0; k < 4; k++) {
        x[k].x -= mu; x[k].y -= mu; x[k].z -= mu; x[k].w -= mu;
        v += x[k].x * x[k].x + x[k].y * x[k].y + x[k].z * x[k].z + x[k].w * x[k].w;
    }
#pragma unroll
    for (int o = 16; o > 0; o >>= 1) v += __shfl_xor_sync(0xffffffffu, v, o);
    const float inv = rsqrtf(v * (1.f / 512.f) + 1e-6f);

#pragma unroll
    for (int k = 0; k < 4; k++) {
        int ci = lane + k * 32;
        float4 gg = g4[ci], bbv = b4[ci];
        o4[ci] = make_float4(x[k].x * inv * gg.x + bbv.x, x[k].y * inv * gg.y + bbv.y,
                             x[k].z * inv * gg.z + bbv.z, x[k].w * inv * gg.w + bbv.w);
    }
}

// ---------------------------------------------------------------------------
extern "C" void kernel_launch(void* const* d_in, const int* in_sizes, int n_in,
                              void* d_out, int out_size)
{
    const float* hs  = (const float*)d_in[0];
    const float* rpe = (const float*)d_in[1];
    const float* Wq  = (const float*)d_in[2];
    const float* Wk  = (const float*)d_in[3];
    const float* Wv  = (const float*)d_in[4];
    const float* fcw = (const float*)d_in[5];
    const float* fcb = (const float*)d_in[6];
    const float* lng = (const float*)d_in[7];
    const float* lnb = (const float*)d_in[8];
    float* out = (float*)d_out;

    cudaFuncSetAttribute(qkv_bf16, cudaFuncAttributeMaxDynamicSharedMemorySize, GEMM_SMEM);
    cudaFuncSetAttribute(fc_bf16,  cudaFuncAttributeMaxDynamicSharedMemorySize, GEMM_SMEM);

    conv_bf16<<<CONV_BLOCKS, 256>>>(hs, Wq, Wk, Wv, fcw);
    qkv_bf16<<<dim3(ROWS / 128, QKVLD / 128), 256, GEMM_SMEM>>>();
    attn_kernel<<<dim3(SEQ / 64, NH, BSZ), 256>>>(rpe);
    fc_bf16<<<dim3(ROWS / 128, DM / 128), 256, GEMM_SMEM>>>();
    ln2_kernel<<<ROWS / 8, 256>>>(hs, fcb, lng, lnb, out);
}

// round 12
// speedup vs baseline: 5.7789x; 2.3057x over previous
#include <cuda_runtime.h>
#include <cuda_bf16.h>
#include <cstdint>

// Problem constants
#define BSZ 8
#define SEQ 1024
#define DM 512
#define NH 8
#define DK 64
#define STATIONS 128
#define ROWS (BSZ * SEQ)          // 8192
#define QKVLD 1536

// Scratch (static device globals)
__device__ float g_qkv[ROWS * QKVLD];           // fp32 q|k|v
__device__ float g_y[ROWS * DM];                // fc output pre-LN
__device__ __nv_bfloat16 g_hsb[ROWS * DM];      // hs bf16
__device__ __nv_bfloat16 g_wb[QKVLD * DM];      // Wq|Wk|Wv stacked bf16
__device__ __nv_bfloat16 g_fwb[DM * DM];        // fc_w bf16
__device__ __nv_bfloat16 g_ctxb[ROWS * DM];     // attention ctx bf16

// ---------------------------------------------------------------------------
// helpers
// ---------------------------------------------------------------------------
__device__ __forceinline__ uint32_t smem_u32(const void* p) {
    uint32_t a;
    asm("{ .reg .u64 t; cvta.to.shared.u64 t, %1; cvt.u32.u64 %0, t; }" : "=r"(a) : "l"(p));
    return a;
}
#define SMEM_SWZ(x) ((x) ^ (((x) >> 3) & 0x70))

__device__ __forceinline__ void ldmx4(uint32_t* r, uint32_t addr) {
    asm volatile("ldmatrix.sync.aligned.m8n8.x4.shared.b16 {%0,%1,%2,%3}, [%4];"
        : "=r"(r[0]), "=r"(r[1]), "=r"(r[2]), "=r"(r[3]) : "r"(addr));
}
__device__ __forceinline__ void mma_bf16(float* c, const uint32_t* a, uint32_t b0, uint32_t b1) {
    asm volatile("mma.sync.aligned.m16n8k16.row.col.f32.bf16.bf16.f32 "
        "{%0,%1,%2,%3},{%4,%5,%6,%7},{%8,%9},{%0,%1,%2,%3};"
        : "+f"(c[0]), "+f"(c[1]), "+f"(c[2]), "+f"(c[3])
        : "r"(a[0]), "r"(a[1]), "r"(a[2]), "r"(a[3]), "r"(b0), "r"(b1));
}
__device__ __forceinline__ void cp16(uint32_t saddr, const void* g) {
    asm volatile("cp.async.cg.shared.global [%0], [%1], 16;" :: "r"(saddr), "l"(g));
}
#define CP_COMMIT() asm volatile("cp.async.commit_group;")
#define CP_WAIT1()  asm volatile("cp.async.wait_group 1;")
#define CP_WAIT0()  asm volatile("cp.async.wait_group 0;")

// ---------------------------------------------------------------------------
// bf16 HMMA GEMM, cp.async 3-stage: C[m0:+128, c0:+128] = A @ B^T (K=512)
// BK=64 (128B rows, SW128), 8 chunks. 256 thr, 8 warps 4x2, warp tile 32x64.
// ---------------------------------------------------------------------------
#define ABYTES 16384                       // 128 rows x 128B
#define STGBYTES (2 * ABYTES)              // A+B per stage = 32KB
#define GEMM_SMEM (3 * STGBYTES)           // 96KB

__device__ __forceinline__ void gemm128_bf16(const __nv_bfloat16* __restrict__ Abase,
                                             const __nv_bfloat16* __restrict__ Bbase,
                                             float* __restrict__ C,
                                             int m0, int c0, int ldc)
{
    extern __shared__ char smem[];
    const uint32_t sb = smem_u32(smem);
    const int tid = threadIdx.x, lane = tid & 31, wid = tid >> 5;
    const int wm = (wid & 3) * 32;
    const int wn = (wid >> 2) * 64;

    const uint4* Ag = (const uint4*)(Abase + (size_t)m0 * DM);
    const uint4* Bg = (const uint4*)Bbase;

    float acc[2][8][4];
#pragma unroll
    for (int i = 0; i < 2; i++)
#pragma unroll
        for (int j = 0; j < 8; j++)
#pragma unroll
            for (int r = 0; r < 4; r++) acc[i][j][r] = 0.f;

    auto cp_chunk = [&](int c, int stg) {
        uint32_t ab = sb + stg * STGBYTES;
        uint32_t bb = ab + ABYTES;
#pragma unroll
        for (int it = 0; it < 4; it++) {
            int idx = tid + it * 256;
            int row = idx >> 3, seg = idx & 7;
            uint32_t so = SMEM_SWZ(row * 128 + seg * 16);
            cp16(ab + so, Ag + row * 64 + c * 8 + seg);
            cp16(bb + so, Bg + row * 64 + c * 8 + seg);
        }
    };
    auto compute = [&](int stg) {
        const uint32_t a_base = sb + stg * STGBYTES;
        const uint32_t b_base = a_base + ABYTES;
        const int lr = lane & 15;
        const int lc = (lane >> 4) << 4;
#pragma unroll
        for (int ks = 0; ks < 4; ks++) {
            const int kb = ks * 32 + lc;
            uint32_t a[2][4];
#pragma unroll
            for (int mt = 0; mt < 2; mt++) {
                int row = wm + mt * 16 + lr;
                ldmx4(a[mt], a_base + SMEM_SWZ(row * 128 + kb));
            }
#pragma unroll
            for (int ng = 0; ng < 4; ng++) {
                uint32_t bf[4];
                int row = wn + ng * 16 + lr;
                ldmx4(bf, b_base + SMEM_SWZ(row * 128 + kb));
#pragma unroll
                for (int mt = 0; mt < 2; mt++) {
                    mma_bf16(acc[mt][ng * 2],     a[mt], bf[0], bf[2]);
                    mma_bf16(acc[mt][ng * 2 + 1], a[mt], bf[1], bf[3]);
                }
            }
        }
    };

    cp_chunk(0, 0); CP_COMMIT();
    cp_chunk(1, 1); CP_COMMIT();
#pragma unroll 1
    for (int c = 0; c < 8; c++) {
        if (c < 7) CP_WAIT1(); else CP_WAIT0();
        __syncthreads();
        if (c < 6) { cp_chunk(c + 2, (c + 2) % 3); CP_COMMIT(); }
        compute(c % 3);
    }

#pragma unroll
    for (int mt = 0; mt < 2; mt++) {
#pragma unroll
        for (int nt = 0; nt < 8; nt++) {
            int row = m0 + wm + mt * 16 + (lane >> 2);
            int col = c0 + wn + nt * 8 + (lane & 3) * 2;
            *(float2*)(C + (size_t)row * ldc + col) =
                make_float2(acc[mt][nt][0], acc[mt][nt][1]);
            *(float2*)(C + (size_t)(row + 8) * ldc + col) =
                make_float2(acc[mt][nt][2], acc[mt][nt][3]);
        }
    }
}

__global__ __launch_bounds__(256, 2) void qkv_bf16()
{
    int m0 = blockIdx.x * 128;
    int gcol = blockIdx.y * 128;
    gemm128_bf16(g_hsb, g_wb + (size_t)gcol * DM, g_qkv, m0, gcol, QKVLD);
}

__global__ __launch_bounds__(256, 2) void fc_bf16()
{
    int m0 = blockIdx.x * 128;
    int n0 = blockIdx.y * 128;
    gemm128_bf16(g_ctxb, g_fwb + (size_t)n0 * DM, g_y, m0, n0, DM);
}

// ---------------------------------------------------------------------------
// fp32 -> bf16 pre-convert (hs, Wq, Wk, Wv stacked, fc_w). vec4 granularity.
// ---------------------------------------------------------------------------
#define HS4   1048576u   // 8192*512/4
#define W4    65536u     // 512*512/4
__global__ __launch_bounds__(256) void conv_bf16(const float* __restrict__ hs,
                                                 const float* __restrict__ Wq,
                                                 const float* __restrict__ Wk,
                                                 const float* __restrict__ Wv,
                                                 const float* __restrict__ fcw)
{
    uint32_t v = blockIdx.x * 256 + threadIdx.x;
    const float4* src;
    __nv_bfloat16* dst;
    if (v < HS4)                  { src = (const float4*)hs  + v;                 dst = g_hsb + (size_t)v * 4; }
    else if (v < HS4 + W4)        { src = (const float4*)Wq  + (v - HS4);         dst = g_wb  + (size_t)(v - HS4) * 4; }
    else if (v < HS4 + 2 * W4)    { src = (const float4*)Wk  + (v - HS4 - W4);    dst = g_wb  + (size_t)(v - HS4 - W4) * 4 + 262144; }
    else if (v < HS4 + 3 * W4)    { src = (const float4*)Wv  + (v - HS4 - 2*W4);  dst = g_wb  + (size_t)(v - HS4 - 2*W4) * 4 + 524288; }
    else                          { src = (const float4*)fcw + (v - HS4 - 3*W4);  dst = g_fwb + (size_t)(v - HS4 - 3*W4) * 4; }
    float4 f = *src;
    __nv_bfloat162 lo = __floats2bfloat162_rn(f.x, f.y);
    __nv_bfloat162 hi = __floats2bfloat162_rn(f.z, f.w);
    *(uint2*)dst = make_uint2(*(uint32_t*)&lo, *(uint32_t*)&hi);
}
#define CONV_BLOCKS ((HS4 + 4 * W4) / 256)

// ---------------------------------------------------------------------------
// Sparse star attention: QK AND PV both via HMMA.
// Smem (dynamic, 51456B), phase-aliased:
//   [0, 33792):  ph1-2 Q(8KB)+K(16KB) bf16 staging -> ph3-4 Ssm f32 [64][132]
//                -> ph5 Vt bf16 [64 d][128 j], 272B row stride
//   [33792, 51200): Pt bf16 [64 q][128 j], 272B row stride  (written in ph4)
//   [51200, 51456): pd f32 [64]
// ---------------------------------------------------------------------------
#define ATT_PT 33792
#define ATT_PD 51200
#define ATT_SMEM 51456

__global__ __launch_bounds__(256) void attn_kernel(const float* __restrict__ rpe)
{
    extern __shared__ char smc[];
    float* sm = (float*)smc;
    const uint32_t sbase = smem_u32(smc);
    const uint32_t sQ = sbase;
    const uint32_t sK = sbase + 8192;

    const int b = blockIdx.z, h = blockIdx.y, qt = blockIdx.x;
    const int tid = threadIdx.x, lane = tid & 31, w = tid >> 5;

    const float* qbase = g_qkv + (size_t)b * SEQ * QKVLD + h * 64;
    const float* kbase = qbase + 512;
    const float* vbase = qbase + 1024;
    const int i0q = qt * 64;

    // ---- Phase 1: stage Q (64x64) and K stations (128x64) bf16, SW128 ----
#pragma unroll
    for (int t = 0; t < 4; t++) {
        int idx4 = tid + t * 256;
        int row = idx4 >> 4, dd = (idx4 & 15) * 4;
        float4 f = *(const float4*)(qbase + (size_t)(i0q + row) * QKVLD + dd);
        __nv_bfloat162 lo = __floats2bfloat162_rn(f.x, f.y);
        __nv_bfloat162 hi = __floats2bfloat162_rn(f.z, f.w);
        *(uint2*)(smc + SMEM_SWZ(row * 128 + dd * 2)) =
            make_uint2(*(uint32_t*)&lo, *(uint32_t*)&hi);
    }
#pragma unroll
    for (int t = 0; t < 8; t++) {
        int idx4 = tid + t * 256;
        int row = idx4 >> 4, dd = (idx4 & 15) * 4;
        float4 f = *(const float4*)(kbase + (size_t)row * QKVLD + dd);
        __nv_bfloat162 lo = __floats2bfloat162_rn(f.x, f.y);
        __nv_bfloat162 hi = __floats2bfloat162_rn(f.z, f.w);
        *(uint2*)(smc + 8192 + SMEM_SWZ(row * 128 + dd * 2)) =
            make_uint2(*(uint32_t*)&lo, *(uint32_t*)&hi);
    }
    __syncthreads();

    // ---- Phase 2: S[64x128] = Q @ K^T (warp grid 4x2: m16, n64) ----
    const int wm16 = (w & 3) * 16;
    const int wn64 = (w >> 2) * 64;
    {
        float acc[8][4];
#pragma unroll
        for (int j = 0; j < 8; j++)
#pragma unroll
            for (int r = 0; r < 4; r++) acc[j][r] = 0.f;
        const int lr = lane & 15;
        const int lc = (lane >> 4) << 4;
#pragma unroll
        for (int ks = 0; ks < 4; ks++) {
            const int kb = ks * 32 + lc;
            uint32_t a4[4];
            ldmx4(a4, sQ + SMEM_SWZ((wm16 + lr) * 128 + kb));
#pragma unroll
            for (int ng = 0; ng < 4; ng++) {
                uint32_t bf[4];
                ldmx4(bf, sK + SMEM_SWZ((wn64 + ng * 16 + lr) * 128 + kb));
                mma_bf16(acc[ng * 2],     a4, bf[0], bf[2]);
                mma_bf16(acc[ng * 2 + 1], a4, bf[1], bf[3]);
            }
        }
        __syncthreads();   // staging consumed; Ssm aliases it

        // ---- Phase 3: S fragments -> Ssm[64][132] fp32 ----
        const int r = wm16 + (lane >> 2);
        const int cb = wn64 + (lane & 3) * 2;
#pragma unroll
        for (int nt = 0; nt < 8; nt++) {
            int c = cb + nt * 8;
            *(float2*)(&sm[r * 132 + c])       = make_float2(acc[nt][0], acc[nt][1]);
            *(float2*)(&sm[(r + 8) * 132 + c]) = make_float2(acc[nt][2], acc[nt][3]);
        }
    }
    __syncthreads();

    // ---- Phase 4: softmax; P -> Pt bf16, PD -> pd[] ----
    const int i0 = i0q + w * 8;
#pragma unroll 1
    for (int qq = 0; qq < 8; qq++) {
        const int i = i0 + qq;
        const int qrowl = w * 8 + qq;
        const float* qrow = qbase + (size_t)i * QKVLD;
        const float qa = qrow[lane], qb = qrow[lane + 32];

        float s[4];
        s[0] = sm[qrowl * 132 + lane];
        s[1] = sm[qrowl * 132 + lane + 32];
        s[2] = sm[qrowl * 132 + lane + 64];
        s[3] = sm[qrowl * 132 + lane + 96];

        const float* rrow = rpe + (((size_t)(b * NH + h) * SEQ + i) * SEQ);
        s[0] += rrow[lane];      s[1] += rrow[lane + 32];
        s[2] += rrow[lane + 64]; s[3] += rrow[lane + 96];

        float sd = 0.f;
        const bool hasd = (i >= STATIONS);
        if (hasd) {
            const float* krow = kbase + (size_t)i * QKVLD;
            float part = qa * krow[lane] + qb * krow[lane + 32];
#pragma unroll
            for (int o = 16; o > 0; o >>= 1) part += __shfl_xor_sync(0xffffffffu, part, o);
            sd = part + rrow[i];
        }

        const float sc = 0.125f;
        float t[4];
        float m = hasd ? sd * sc : -1e30f;
#pragma unroll
        for (int r = 0; r < 4; r++) { t[r] = s[r] * sc; m = fmaxf(m, t[r]); }
#pragma unroll
        for (int o = 16; o > 0; o >>= 1) m = fmaxf(m, __shfl_xor_sync(0xffffffffu, m, o));
        float e[4], sum = 0.f;
#pragma unroll
        for (int r = 0; r < 4; r++) { e[r] = __expf(t[r] - m); sum += e[r]; }
#pragma unroll
        for (int o = 16; o > 0; o >>= 1) sum += __shfl_xor_sync(0xffffffffu, sum, o);
        float ed = hasd ? __expf(sd * sc - m) : 0.f;
        sum += ed;
        float inv = 1.f / sum;

#pragma unroll
        for (int r = 0; r < 4; r++) {
            *(__nv_bfloat16*)(smc + ATT_PT + qrowl * 272 + (lane + 32 * r) * 2) =
                __float2bfloat16_rn(e[r] * inv);
        }
        if (lane == 0) ((float*)(smc + ATT_PD))[qrowl] = ed * inv;
    }
    __syncthreads();   // Ssm consumed; Vt aliases it

    // ---- Phase 5a: stage Vt[d][j] bf16 (transposed V), 272B rows ----
#pragma unroll 4
    for (int it = 0; it < 32; it++) {
        int idx = tid + it * 256;
        int d = idx & 63, j = idx >> 6;
        float v = vbase[(size_t)j * QKVLD + d];
        *(__nv_bfloat16*)(smc + d * 272 + j * 2) = __float2bfloat16_rn(v);
    }
    __syncthreads();

    // ---- Phase 5b: ctx[64x64] = P @ Vt^T (warp grid 4x2: m16, n32) ----
    const int wn32 = (w >> 2) * 32;
    float acc2[4][4];
#pragma unroll
    for (int j = 0; j < 4; j++)
#pragma unroll
        for (int r = 0; r < 4; r++) acc2[j][r] = 0.f;
    {
        const int lr = lane & 15;
        const int lc = (lane >> 4) << 4;
#pragma unroll
        for (int kc = 0; kc < 8; kc++) {
            const int kb = kc * 32 + lc;
            uint32_t ap[4];
            ldmx4(ap, sbase + ATT_PT + (wm16 + lr) * 272 + kb);
#pragma unroll
            for (int ng = 0; ng < 2; ng++) {
                uint32_t bv[4];
                ldmx4(bv, sbase + (wn32 + ng * 16 + lr) * 272 + kb);
                mma_bf16(acc2[ng * 2],     ap, bv[0], bv[2]);
                mma_bf16(acc2[ng * 2 + 1], ap, bv[1], bv[3]);
            }
        }
    }

    // ---- Epilogue: diagonal term + bf16 ctx stores ----
    const float* pdArr = (const float*)(smc + ATT_PD);
#pragma unroll
    for (int half = 0; half < 2; half++) {
        int rloc = wm16 + (lane >> 2) + half * 8;
        int i = i0q + rloc;
        float pdv = (i >= STATIONS) ? pdArr[rloc] : 0.f;
        const float* vrow = vbase + (size_t)i * QKVLD;
        __nv_bfloat16* crow = g_ctxb + (((size_t)b * SEQ + i) * NH + h) * 64;
#pragma unroll
        for (int nt = 0; nt < 4; nt++) {
            int col = wn32 + nt * 8 + (lane & 3) * 2;
            float c0 = acc2[nt][half * 2 + 0];
            float c1 = acc2[nt][half * 2 + 1];
            if (i >= STATIONS) {
                c0 += pdv * vrow[col];
                c1 += pdv * vrow[col + 1];
            }
            *(__nv_bfloat162*)(crow + col) = __floats2bfloat162_rn(c0, c1);
        }
    }
}

// ---------------------------------------------------------------------------
// bias + residual + LayerNorm: one warp per row, shuffle-only reductions.
// ---------------------------------------------------------------------------
__global__ __launch_bounds__(256) void ln2_kernel(const float* __restrict__ resid,
                                                  const float* __restrict__ fcb,
                                                  const float* __restrict__ g,
                                                  const float* __restrict__ bb,
                                                  float* __restrict__ out)
{
    const int lane = threadIdx.x & 31;
    const int row = blockIdx.x * 8 + (threadIdx.x >> 5);
    const float4* y4 = (const float4*)(g_y + (size_t)row * DM);
    const float4* r4 = (const float4*)(resid + (size_t)row * DM);
    const float4* f4 = (const float4*)fcb;
    const float4* g4 = (const float4*)g;
    const float4* b4 = (const float4*)bb;
    float4* o4 = (float4*)(out + (size_t)row * DM);

    float4 x[4];
    float s = 0.f;
#pragma unroll
    for (int k = 0; k < 4; k++) {
        int ci = lane + k * 32;
        float4 a = y4[ci], rr = r4[ci], ff = f4[ci];
        x[k] = make_float4(a.x + rr.x + ff.x, a.y + rr.y + ff.y,
                           a.z + rr.z + ff.z, a.w + rr.w + ff.w);
        s += x[k].x + x[k].y + x[k].z + x[k].w;
    }
#pragma unroll
    for (int o = 16; o > 0; o >>= 1) s += __shfl_xor_sync(0xffffffffu, s, o);
    const float mu = s * (1.f / 512.f);

    float v = 0.f;
#pragma unroll
    for (int k = 0; k < 4; k++) {
        x[k].x -= mu; x[k].y -= mu; x[k].z -= mu; x[k].w -= mu;
        v += x[k].x * x[k].x + x[k].y * x[k].y + x[k].z * x[k].z + x[k].w * x[k].w;
    }
#pragma unroll
    for (int o = 16; o > 0; o >>= 1) v += __shfl_xor_sync(0xffffffffu, v, o);
    const float inv = rsqrtf(v * (1.f / 512.f) + 1e-6f);

#pragma unroll
    for (int k = 0; k < 4; k++) {
        int ci = lane + k * 32;
        float4 gg = g4[ci], bbv = b4[ci];
        o4[ci] = make_float4(x[k].x * inv * gg.x + bbv.x, x[k].y * inv * gg.y + bbv.y,
                             x[k].z * inv * gg.z + bbv.z, x[k].w * inv * gg.w + bbv.w);
    }
}

// ---------------------------------------------------------------------------
extern "C" void kernel_launch(void* const* d_in, const int* in_sizes, int n_in,
                              void* d_out, int out_size)
{
    const float* hs  = (const float*)d_in[0];
    const float* rpe = (const float*)d_in[1];
    const float* Wq  = (const float*)d_in[2];
    const float* Wk  = (const float*)d_in[3];
    const float* Wv  = (const float*)d_in[4];
    const float* fcw = (const float*)d_in[5];
    const float* fcb = (const float*)d_in[6];
    const float* lng = (const float*)d_in[7];
    const float* lnb = (const float*)d_in[8];
    float* out = (float*)d_out;

    cudaFuncSetAttribute(qkv_bf16, cudaFuncAttributeMaxDynamicSharedMemorySize, GEMM_SMEM);
    cudaFuncSetAttribute(fc_bf16,  cudaFuncAttributeMaxDynamicSharedMemorySize, GEMM_SMEM);
    cudaFuncSetAttribute(attn_kernel, cudaFuncAttributeMaxDynamicSharedMemorySize, ATT_SMEM);

    conv_bf16<<<CONV_BLOCKS, 256>>>(hs, Wq, Wk, Wv, fcw);
    qkv_bf16<<<dim3(ROWS / 128, QKVLD / 128), 256, GEMM_SMEM>>>();
    attn_kernel<<<dim3(SEQ / 64, NH, BSZ), 256, ATT_SMEM>>>(rpe);
    fc_bf16<<<dim3(ROWS / 128, DM / 128), 256, GEMM_SMEM>>>();
    ln2_kernel<<<ROWS / 8, 256>>>(hs, fcb, lng, lnb, out);
}

// round 15
// speedup vs baseline: 5.7927x; 1.0024x over previous
#include <cuda_runtime.h>
#include <cuda_bf16.h>
#include <cstdint>

// Problem constants
#define BSZ 8
#define SEQ 1024
#define DM 512
#define NH 8
#define DK 64
#define STATIONS 128
#define ROWS (BSZ * SEQ)          // 8192
#define QKVLD 1536

// Scratch (static device globals)
__device__ __nv_bfloat16 g_qkvb[ROWS * QKVLD];  // bf16 q|k|v
__device__ float g_y[ROWS * DM];                // fc output pre-LN
__device__ __nv_bfloat16 g_hsb[ROWS * DM];      // hs bf16
__device__ __nv_bfloat16 g_wb[QKVLD * DM];      // Wq|Wk|Wv stacked bf16
__device__ __nv_bfloat16 g_fwb[DM * DM];        // fc_w bf16
__device__ __nv_bfloat16 g_ctxb[ROWS * DM];     // attention ctx bf16

// ---------------------------------------------------------------------------
// helpers
// ---------------------------------------------------------------------------
__device__ __forceinline__ uint32_t smem_u32(const void* p) {
    uint32_t a;
    asm("{ .reg .u64 t; cvta.to.shared.u64 t, %1; cvt.u32.u64 %0, t; }" : "=r"(a) : "l"(p));
    return a;
}
#define SMEM_SWZ(x) ((x) ^ (((x) >> 3) & 0x70))

__device__ __forceinline__ void ldmx4(uint32_t* r, uint32_t addr) {
    asm volatile("ldmatrix.sync.aligned.m8n8.x4.shared.b16 {%0,%1,%2,%3}, [%4];"
        : "=r"(r[0]), "=r"(r[1]), "=r"(r[2]), "=r"(r[3]) : "r"(addr));
}
__device__ __forceinline__ void mma_bf16(float* c, const uint32_t* a, uint32_t b0, uint32_t b1) {
    asm volatile("mma.sync.aligned.m16n8k16.row.col.f32.bf16.bf16.f32 "
        "{%0,%1,%2,%3},{%4,%5,%6,%7},{%8,%9},{%0,%1,%2,%3};"
        : "+f"(c[0]), "+f"(c[1]), "+f"(c[2]), "+f"(c[3])
        : "r"(a[0]), "r"(a[1]), "r"(a[2]), "r"(a[3]), "r"(b0), "r"(b1));
}
__device__ __forceinline__ void cp16(uint32_t saddr, const void* g) {
    asm volatile("cp.async.cg.shared.global [%0], [%1], 16;" :: "r"(saddr), "l"(g));
}
#define CP_COMMIT() asm volatile("cp.async.commit_group;")
#define CP_WAIT1()  asm volatile("cp.async.wait_group 1;")
#define CP_WAIT0()  asm volatile("cp.async.wait_group 0;")

// ---------------------------------------------------------------------------
// bf16 HMMA GEMM, cp.async 3-stage: C[m0:+128, c0:+128] = A @ B^T (K=512)
// BK=64 (128B rows, SW128), 8 chunks. 256 thr, 8 warps 4x2, warp tile 32x64.
// BF16OUT selects bf16 vs fp32 C stores.
// ---------------------------------------------------------------------------
#define ABYTES 16384                       // 128 rows x 128B
#define STGBYTES (2 * ABYTES)              // A+B per stage = 32KB
#define GEMM_SMEM (3 * STGBYTES)           // 96KB

template<bool BF16OUT>
__device__ __forceinline__ void gemm128_bf16(const __nv_bfloat16* __restrict__ Abase,
                                             const __nv_bfloat16* __restrict__ Bbase,
                                             void* __restrict__ Cv,
                                             int m0, int c0, int ldc)
{
    extern __shared__ char smem[];
    const uint32_t sb = smem_u32(smem);
    const int tid = threadIdx.x, lane = tid & 31, wid = tid >> 5;
    const int wm = (wid & 3) * 32;
    const int wn = (wid >> 2) * 64;

    const uint4* Ag = (const uint4*)(Abase + (size_t)m0 * DM);
    const uint4* Bg = (const uint4*)Bbase;

    float acc[2][8][4];
#pragma unroll
    for (int i = 0; i < 2; i++)
#pragma unroll
        for (int j = 0; j < 8; j++)
#pragma unroll
            for (int r = 0; r < 4; r++) acc[i][j][r] = 0.f;

    auto cp_chunk = [&](int c, int stg) {
        uint32_t ab = sb + stg * STGBYTES;
        uint32_t bb = ab + ABYTES;
#pragma unroll
        for (int it = 0; it < 4; it++) {
            int idx = tid + it * 256;
            int row = idx >> 3, seg = idx & 7;
            uint32_t so = SMEM_SWZ(row * 128 + seg * 16);
            cp16(ab + so, Ag + row * 64 + c * 8 + seg);
            cp16(bb + so, Bg + row * 64 + c * 8 + seg);
        }
    };
    auto compute = [&](int stg) {
        const uint32_t a_base = sb + stg * STGBYTES;
        const uint32_t b_base = a_base + ABYTES;
        const int lr = lane & 15;
        const int lc = (lane >> 4) << 4;
#pragma unroll
        for (int ks = 0; ks < 4; ks++) {
            const int kb = ks * 32 + lc;
            uint32_t a[2][4];
#pragma unroll
            for (int mt = 0; mt < 2; mt++) {
                int row = wm + mt * 16 + lr;
                ldmx4(a[mt], a_base + SMEM_SWZ(row * 128 + kb));
            }
#pragma unroll
            for (int ng = 0; ng < 4; ng++) {
                uint32_t bf[4];
                int row = wn + ng * 16 + lr;
                ldmx4(bf, b_base + SMEM_SWZ(row * 128 + kb));
#pragma unroll
                for (int mt = 0; mt < 2; mt++) {
                    mma_bf16(acc[mt][ng * 2],     a[mt], bf[0], bf[2]);
                    mma_bf16(acc[mt][ng * 2 + 1], a[mt], bf[1], bf[3]);
                }
            }
        }
    };

    cp_chunk(0, 0); CP_COMMIT();
    cp_chunk(1, 1); CP_COMMIT();
#pragma unroll 1
    for (int c = 0; c < 8; c++) {
        if (c < 7) CP_WAIT1(); else CP_WAIT0();
        __syncthreads();
        if (c < 6) { cp_chunk(c + 2, (c + 2) % 3); CP_COMMIT(); }
        compute(c % 3);
    }

#pragma unroll
    for (int mt = 0; mt < 2; mt++) {
#pragma unroll
        for (int nt = 0; nt < 8; nt++) {
            int row = m0 + wm + mt * 16 + (lane >> 2);
            int col = c0 + wn + nt * 8 + (lane & 3) * 2;
            if constexpr (BF16OUT) {
                __nv_bfloat16* C = (__nv_bfloat16*)Cv;
                *(__nv_bfloat162*)(C + (size_t)row * ldc + col) =
                    __floats2bfloat162_rn(acc[mt][nt][0], acc[mt][nt][1]);
                *(__nv_bfloat162*)(C + (size_t)(row + 8) * ldc + col) =
                    __floats2bfloat162_rn(acc[mt][nt][2], acc[mt][nt][3]);
            } else {
                float* C = (float*)Cv;
                *(float2*)(C + (size_t)row * ldc + col) =
                    make_float2(acc[mt][nt][0], acc[mt][nt][1]);
                *(float2*)(C + (size_t)(row + 8) * ldc + col) =
                    make_float2(acc[mt][nt][2], acc[mt][nt][3]);
            }
        }
    }
}

__global__ __launch_bounds__(256, 2) void qkv_bf16()
{
    int m0 = blockIdx.x * 128;
    int gcol = blockIdx.y * 128;
    gemm128_bf16<true>(g_hsb, g_wb + (size_t)gcol * DM, g_qkvb, m0, gcol, QKVLD);
}

__global__ __launch_bounds__(256, 2) void fc_bf16()
{
    int m0 = blockIdx.x * 128;
    int n0 = blockIdx.y * 128;
    gemm128_bf16<false>(g_ctxb, g_fwb + (size_t)n0 * DM, g_y, m0, n0, DM);
}

// ---------------------------------------------------------------------------
// fp32 -> bf16 pre-convert (hs, Wq, Wk, Wv stacked, fc_w). vec4 granularity.
// ---------------------------------------------------------------------------
#define HS4   1048576u   // 8192*512/4
#define W4    65536u     // 512*512/4
__global__ __launch_bounds__(256) void conv_bf16(const float* __restrict__ hs,
                                                 const float* __restrict__ Wq,
                                                 const float* __restrict__ Wk,
                                                 const float* __restrict__ Wv,
                                                 const float* __restrict__ fcw)
{
    uint32_t v = blockIdx.x * 256 + threadIdx.x;
    const float4* src;
    __nv_bfloat16* dst;
    if (v < HS4)                  { src = (const float4*)hs  + v;                 dst = g_hsb + (size_t)v * 4; }
    else if (v < HS4 + W4)        { src = (const float4*)Wq  + (v - HS4);         dst = g_wb  + (size_t)(v - HS4) * 4; }
    else if (v < HS4 + 2 * W4)    { src = (const float4*)Wk  + (v - HS4 - W4);    dst = g_wb  + (size_t)(v - HS4 - W4) * 4 + 262144; }
    else if (v < HS4 + 3 * W4)    { src = (const float4*)Wv  + (v - HS4 - 2*W4);  dst = g_wb  + (size_t)(v - HS4 - 2*W4) * 4 + 524288; }
    else                          { src = (const float4*)fcw + (v - HS4 - 3*W4);  dst = g_fwb + (size_t)(v - HS4 - 3*W4) * 4; }
    float4 f = *src;
    __nv_bfloat162 lo = __floats2bfloat162_rn(f.x, f.y);
    __nv_bfloat162 hi = __floats2bfloat162_rn(f.z, f.w);
    *(uint2*)dst = make_uint2(*(uint32_t*)&lo, *(uint32_t*)&hi);
}
#define CONV_BLOCKS ((HS4 + 4 * W4) / 256)

// ---------------------------------------------------------------------------
// Sparse star attention: QK AND PV both via HMMA; qkv is bf16 (direct copies).
// Smem (dynamic, 51456B), phase-aliased:
//   [0, 33792):  ph1-2 Q(8KB)+K(16KB) bf16 staging -> ph3-4 Ssm f32 [64][132]
//                -> ph5 Vt bf16 [64 d][128 j], 272B row stride
//   [33792, 51200): Pt bf16 [64 q][128 j], 272B row stride  (written in ph4)
//   [51200, 51456): pd f32 [64]
// ---------------------------------------------------------------------------
#define ATT_PT 33792
#define ATT_PD 51200
#define ATT_SMEM 51456

__global__ __launch_bounds__(256) void attn_kernel(const float* __restrict__ rpe)
{
    extern __shared__ char smc[];
    float* sm = (float*)smc;
    const uint32_t sbase = smem_u32(smc);
    const uint32_t sQ = sbase;
    const uint32_t sK = sbase + 8192;

    const int b = blockIdx.z, h = blockIdx.y, qt = blockIdx.x;
    const int tid = threadIdx.x, lane = tid & 31, w = tid >> 5;

    const __nv_bfloat16* qbase = g_qkvb + (size_t)b * SEQ * QKVLD + h * 64;
    const __nv_bfloat16* kbase = qbase + 512;
    const __nv_bfloat16* vbase = qbase + 1024;
    const int i0q = qt * 64;

    // ---- Phase 1: stage Q (64 rows) and K (128 rows), 128B bf16 rows, SW128 ----
#pragma unroll
    for (int t = 0; t < 2; t++) {                  // Q: 512 uint4
        int idx = tid + t * 256;
        int row = idx >> 3, seg = idx & 7;
        uint4 v = *(const uint4*)(qbase + (size_t)(i0q + row) * QKVLD + seg * 8);
        *(uint4*)(smc + SMEM_SWZ(row * 128 + seg * 16)) = v;
    }
#pragma unroll
    for (int t = 0; t < 4; t++) {                  // K: 1024 uint4
        int idx = tid + t * 256;
        int row = idx >> 3, seg = idx & 7;
        uint4 v = *(const uint4*)(kbase + (size_t)row * QKVLD + seg * 8);
        *(uint4*)(smc + 8192 + SMEM_SWZ(row * 128 + seg * 16)) = v;
    }
    __syncthreads();

    // ---- Phase 2: S[64x128] = Q @ K^T (warp grid 4x2: m16, n64) ----
    const int wm16 = (w & 3) * 16;
    const int wn64 = (w >> 2) * 64;
    {
        float acc[8][4];
#pragma unroll
        for (int j = 0; j < 8; j++)
#pragma unroll
            for (int r = 0; r < 4; r++) acc[j][r] = 0.f;
        const int lr = lane & 15;
        const int lc = (lane >> 4) << 4;
#pragma unroll
        for (int ks = 0; ks < 4; ks++) {
            const int kb = ks * 32 + lc;
            uint32_t a4[4];
            ldmx4(a4, sQ + SMEM_SWZ((wm16 + lr) * 128 + kb));
#pragma unroll
            for (int ng = 0; ng < 4; ng++) {
                uint32_t bf[4];
                ldmx4(bf, sK + SMEM_SWZ((wn64 + ng * 16 + lr) * 128 + kb));
                mma_bf16(acc[ng * 2],     a4, bf[0], bf[2]);
                mma_bf16(acc[ng * 2 + 1], a4, bf[1], bf[3]);
            }
        }
        __syncthreads();   // staging consumed; Ssm aliases it

        // ---- Phase 3: S fragments -> Ssm[64][132] fp32 ----
        const int r = wm16 + (lane >> 2);
        const int cb = wn64 + (lane & 3) * 2;
#pragma unroll
        for (int nt = 0; nt < 8; nt++) {
            int c = cb + nt * 8;
            *(float2*)(&sm[r * 132 + c])       = make_float2(acc[nt][0], acc[nt][1]);
            *(float2*)(&sm[(r + 8) * 132 + c]) = make_float2(acc[nt][2], acc[nt][3]);
        }
    }
    __syncthreads();

    // ---- Phase 4: softmax; P -> Pt bf16, PD -> pd[] ----
    const int i0 = i0q + w * 8;
#pragma unroll 1
    for (int qq = 0; qq < 8; qq++) {
        const int i = i0 + qq;
        const int qrowl = w * 8 + qq;

        float s[4];
        s[0] = sm[qrowl * 132 + lane];
        s[1] = sm[qrowl * 132 + lane + 32];
        s[2] = sm[qrowl * 132 + lane + 64];
        s[3] = sm[qrowl * 132 + lane + 96];

        const float* rrow = rpe + (((size_t)(b * NH + h) * SEQ + i) * SEQ);
        s[0] += rrow[lane];      s[1] += rrow[lane + 32];
        s[2] += rrow[lane + 64]; s[3] += rrow[lane + 96];

        float sd = 0.f;
        const bool hasd = (i >= STATIONS);
        if (hasd) {
            const __nv_bfloat16* qrow = qbase + (size_t)i * QKVLD;
            const __nv_bfloat16* krow = kbase + (size_t)i * QKVLD;
            float part = __bfloat162float(qrow[lane]) * __bfloat162float(krow[lane])
                       + __bfloat162float(qrow[lane + 32]) * __bfloat162float(krow[lane + 32]);
#pragma unroll
            for (int o = 16; o > 0; o >>= 1) part += __shfl_xor_sync(0xffffffffu, part, o);
            sd = part + rrow[i];
        }

        const float sc = 0.125f;
        float t[4];
        float m = hasd ? sd * sc : -1e30f;
#pragma unroll
        for (int r = 0; r < 4; r++) { t[r] = s[r] * sc; m = fmaxf(m, t[r]); }
#pragma unroll
        for (int o = 16; o > 0; o >>= 1) m = fmaxf(m, __shfl_xor_sync(0xffffffffu, m, o));
        float e[4], sum = 0.f;
#pragma unroll
        for (int r = 0; r < 4; r++) { e[r] = __expf(t[r] - m); sum += e[r]; }
#pragma unroll
        for (int o = 16; o > 0; o >>= 1) sum += __shfl_xor_sync(0xffffffffu, sum, o);
        float ed = hasd ? __expf(sd * sc - m) : 0.f;
        sum += ed;
        float inv = 1.f / sum;

#pragma unroll
        for (int r = 0; r < 4; r++) {
            *(__nv_bfloat16*)(smc + ATT_PT + qrowl * 272 + (lane + 32 * r) * 2) =
                __float2bfloat16_rn(e[r] * inv);
        }
        if (lane == 0) ((float*)(smc + ATT_PD))[qrowl] = ed * inv;
    }
    __syncthreads();   // Ssm consumed; Vt aliases it

    // ---- Phase 5a: stage Vt[d][j] bf16 (transposed V), 272B rows ----
#pragma unroll 4
    for (int it = 0; it < 16; it++) {
        int idx = tid + it * 256;               // 4096 bf162 elements
        int d2 = idx & 31, j = idx >> 5;        // d = 2*d2
        uint32_t pv = *(const uint32_t*)(vbase + (size_t)j * QKVLD + d2 * 2);
        *(__nv_bfloat16*)(smc + (d2 * 2)     * 272 + j * 2) = ((__nv_bfloat162*)&pv)->x;
        *(__nv_bfloat16*)(smc + (d2 * 2 + 1) * 272 + j * 2) = ((__nv_bfloat162*)&pv)->y;
    }
    __syncthreads();

    // ---- Phase 5b: ctx[64x64] = P @ Vt^T (warp grid 4x2: m16, n32) ----
    const int wn32 = (w >> 2) * 32;
    float acc2[4][4];
#pragma unroll
    for (int j = 0; j < 4; j++)
#pragma unroll
        for (int r = 0; r < 4; r++) acc2[j][r] = 0.f;
    {
        const int lr = lane & 15;
        const int lc = (lane >> 4) << 4;
#pragma unroll
        for (int kc = 0; kc < 8; kc++) {
            const int kb = kc * 32 + lc;
            uint32_t ap[4];
            ldmx4(ap, sbase + ATT_PT + (wm16 + lr) * 272 + kb);
#pragma unroll
            for (int ng = 0; ng < 2; ng++) {
                uint32_t bv[4];
                ldmx4(bv, sbase + (wn32 + ng * 16 + lr) * 272 + kb);
                mma_bf16(acc2[ng * 2],     ap, bv[0], bv[2]);
                mma_bf16(acc2[ng * 2 + 1], ap, bv[1], bv[3]);
            }
        }
    }

    // ---- Epilogue: diagonal term + bf16 ctx stores ----
    const float* pdArr = (const float*)(smc + ATT_PD);
#pragma unroll
    for (int half = 0; half < 2; half++) {
        int rloc = wm16 + (lane >> 2) + half * 8;
        int i = i0q + rloc;
        float pdv = (i >= STATIONS) ? pdArr[rloc] : 0.f;
        const __nv_bfloat16* vrow = vbase + (size_t)i * QKVLD;
        __nv_bfloat16* crow = g_ctxb + (((size_t)b * SEQ + i) * NH + h) * 64;
#pragma unroll
        for (int nt = 0; nt < 4; nt++) {
            int col = wn32 + nt * 8 + (lane & 3) * 2;
            float c0 = acc2[nt][half * 2 + 0];
            float c1 = acc2[nt][half * 2 + 1];
            if (i >= STATIONS) {
                c0 += pdv * __bfloat162float(vrow[col]);
                c1 += pdv * __bfloat162float(vrow[col + 1]);
            }
            *(__nv_bfloat162*)(crow + col) = __floats2bfloat162_rn(c0, c1);
        }
    }
}

// ---------------------------------------------------------------------------
// bias + residual + LayerNorm: one warp per row, shuffle-only reductions.
// ---------------------------------------------------------------------------
__global__ __launch_bounds__(256) void ln2_kernel(const float* __restrict__ resid,
                                                  const float* __restrict__ fcb,
                                                  const float* __restrict__ g,
                                                  const float* __restrict__ bb,
                                                  float* __restrict__ out)
{
    const int lane = threadIdx.x & 31;
    const int row = blockIdx.x * 8 + (threadIdx.x >> 5);
    const float4* y4 = (const float4*)(g_y + (size_t)row * DM);
    const float4* r4 = (const float4*)(resid + (size_t)row * DM);
    const float4* f4 = (const float4*)fcb;
    const float4* g4 = (const float4*)g;
    const float4* b4 = (const float4*)bb;
    float4* o4 = (float4*)(out + (size_t)row * DM);

    float4 x[4];
    float s = 0.f;
#pragma unroll
    for (int k = 0; k < 4; k++) {
        int ci = lane + k * 32;
        float4 a = y4[ci], rr = r4[ci], ff = f4[ci];
        x[k] = make_float4(a.x + rr.x + ff.x, a.y + rr.y + ff.y,
                           a.z + rr.z + ff.z, a.w + rr.w + ff.w);
        s += x[k].x + x[k].y + x[k].z + x[k].w;
    }
#pragma unroll
    for (int o = 16; o > 0; o >>= 1) s += __shfl_xor_sync(0xffffffffu, s, o);
    const float mu = s * (1.f / 512.f);

    float v = 0.f;
#pragma unroll
    for (int k = 0; k < 4; k++) {
        x[k].x -= mu; x[k].y -= mu; x[k].z -= mu; x[k].w -= mu;
        v += x[k].x * x[k].x + x[k].y * x[k].y + x[k].z * x[k].z + x[k].w * x[k].w;
    }
#pragma unroll
    for (int o = 16; o > 0; o >>= 1) v += __shfl_xor_sync(0xffffffffu, v, o);
    const float inv = rsqrtf(v * (1.f / 512.f) + 1e-6f);

#pragma unroll
    for (int k = 0; k < 4; k++) {
        int ci = lane + k * 32;
        float4 gg = g4[ci], bbv = b4[ci];
        o4[ci] = make_float4(x[k].x * inv * gg.x + bbv.x, x[k].y * inv * gg.y + bbv.y,
                             x[k].z * inv * gg.z + bbv.z, x[k].w * inv * gg.w + bbv.w);
    }
}

// ---------------------------------------------------------------------------
extern "C" void kernel_launch(void* const* d_in, const int* in_sizes, int n_in,
                              void* d_out, int out_size)
{
    const float* hs  = (const float*)d_in[0];
    const float* rpe = (const float*)d_in[1];
    const float* Wq  = (const float*)d_in[2];
    const float* Wk  = (const float*)d_in[3];
    const float* Wv  = (const float*)d_in[4];
    const float* fcw = (const float*)d_in[5];
    const float* fcb = (const float*)d_in[6];
    const float* lng = (const float*)d_in[7];
    const float* lnb = (const float*)d_in[8];
    float* out = (float*)d_out;

    cudaFuncSetAttribute(qkv_bf16, cudaFuncAttributeMaxDynamicSharedMemorySize, GEMM_SMEM);
    cudaFuncSetAttribute(fc_bf16,  cudaFuncAttributeMaxDynamicSharedMemorySize, GEMM_SMEM);
    cudaFuncSetAttribute(attn_kernel, cudaFuncAttributeMaxDynamicSharedMemorySize, ATT_SMEM);

    conv_bf16<<<CONV_BLOCKS, 256>>>(hs, Wq, Wk, Wv, fcw);
    qkv_bf16<<<dim3(ROWS / 128, QKVLD / 128), 256, GEMM_SMEM>>>();
    attn_kernel<<<dim3(SEQ / 64, NH, BSZ), 256, ATT_SMEM>>>(rpe);
    fc_bf16<<<dim3(ROWS / 128, DM / 128), 256, GEMM_SMEM>>>();
    ln2_kernel<<<ROWS / 8, 256>>>(hs, fcb, lng, lnb, out);
}